// round 1
// baseline (speedup 1.0000x reference)
#include <cuda_runtime.h>
#include <math_constants.h>

// contributions: [S=256, P=2000, C=200] fp32, row-major (c contiguous).
// Per (s, c) column along P: zero the top-4 values (stable ties -> lower p),
// pass everything else through.
//
// One thread per (s, c) column. Consecutive threads = consecutive c =
// coalesced 128B warp transactions at each p. Single pass: copy while
// tracking top-4 (value, index) in registers, then patch 4 zeros.

static constexpr int S = 256;
static constexpr int P = 2000;
static constexpr int C = 200;
static constexpr int NCOL = S * C;      // 51200 threads
static constexpr int U = 16;            // unroll: 2000 = 125 * 16

__global__ void __launch_bounds__(128, 16)
numproto_topk_zero(const float* __restrict__ in, float* __restrict__ out) {
    int gid = blockIdx.x * blockDim.x + threadIdx.x;
    if (gid >= NCOL) return;

    int s = gid / C;
    int c = gid - s * C;

    const float* ip = in  + (size_t)s * P * C + c;
    float*       op = out + (size_t)s * P * C + c;

    // top-4 descending: t0 >= t1 >= t2 >= t3; strict > on insert reproduces
    // stable argsort tie-breaking (earlier p wins).
    float t0 = -CUDART_INF_F, t1 = -CUDART_INF_F,
          t2 = -CUDART_INF_F, t3 = -CUDART_INF_F;
    int   i0 = 0, i1 = 0, i2 = 0, i3 = 0;

    for (int p = 0; p < P; p += U) {
        float v[U];
        // batch loads first for MLP
        #pragma unroll
        for (int u = 0; u < U; u++)
            v[u] = ip[(size_t)(p + u) * C];
        // passthrough copy
        #pragma unroll
        for (int u = 0; u < U; u++)
            op[(size_t)(p + u) * C] = v[u];
        // top-4 update (common case: one compare, no insert)
        #pragma unroll
        for (int u = 0; u < U; u++) {
            float vv = v[u];
            if (vv > t3) {
                int pp = p + u;
                if (vv > t0) {
                    t3 = t2; i3 = i2; t2 = t1; i2 = i1; t1 = t0; i1 = i0;
                    t0 = vv; i0 = pp;
                } else if (vv > t1) {
                    t3 = t2; i3 = i2; t2 = t1; i2 = i1;
                    t1 = vv; i1 = pp;
                } else if (vv > t2) {
                    t3 = t2; i3 = i2;
                    t2 = vv; i2 = pp;
                } else {
                    t3 = vv; i3 = pp;
                }
            }
        }
    }

    // patch the 4 winners to zero (same thread wrote them; ordering is safe)
    op[(size_t)i0 * C] = 0.0f;
    op[(size_t)i1 * C] = 0.0f;
    op[(size_t)i2 * C] = 0.0f;
    op[(size_t)i3 * C] = 0.0f;
}

extern "C" void kernel_launch(void* const* d_in, const int* in_sizes, int n_in,
                              void* d_out, int out_size) {
    (void)in_sizes; (void)n_in; (void)out_size;
    const float* in  = (const float*)d_in[0];
    float*       out = (float*)d_out;
    constexpr int BLK = 128;
    constexpr int GRID = (NCOL + BLK - 1) / BLK;  // 400 blocks
    numproto_topk_zero<<<GRID, BLK>>>(in, out);
}

// round 2
// speedup vs baseline: 1.4529x; 1.4529x over previous
#include <cuda_runtime.h>
#include <math_constants.h>

// contributions: [S=256, P=2000, C=200] fp32, row-major (c contiguous).
// Per (s, c) column along P: zero the top-4 values (stable ties -> lower p),
// pass everything else through.
//
// R2: 4 warps cooperate on 32 columns (one warp per P-segment of 500) to get
// 204800 threads (~43 warps/SM, single wave) instead of 51200 (~11 warps/SM).
// Segment-local top-4 in registers, merged via conflict-free smem, stable
// tie-break (value desc, index asc). Patch 4 zeros after __syncthreads().

static constexpr int S = 256;
static constexpr int P = 2000;
static constexpr int C = 200;
static constexpr int NCOL = S * C;          // 51200 columns
static constexpr int SEG  = 4;              // warps (segments) per column group
static constexpr int PSEG = P / SEG;        // 500
static constexpr int U    = 10;             // 500 = 50 * 10
static constexpr int COLS = 32;             // columns per block
static constexpr int BLK  = COLS * SEG;     // 128 threads
static constexpr int GRID = NCOL / COLS;    // 1600 blocks

__global__ void __launch_bounds__(BLK, 12)
numproto_topk_zero(const float* __restrict__ in, float* __restrict__ out) {
    const int tid  = threadIdx.x;
    const int seg  = tid >> 5;              // 0..3
    const int lane = tid & 31;              // column within block
    const int col  = blockIdx.x * COLS + lane;   // 0..51199

    const int s = col / C;
    const int c = col - s * C;

    const float* ip = in  + (size_t)s * P * C + c;
    float*       op = out + (size_t)s * P * C + c;

    // segment-local top-4 (descending); strict > keeps earliest p on ties
    float t0 = -CUDART_INF_F, t1 = -CUDART_INF_F,
          t2 = -CUDART_INF_F, t3 = -CUDART_INF_F;
    int   i0 = 0, i1 = 0, i2 = 0, i3 = 0;

    const int p0 = seg * PSEG;
    for (int p = p0; p < p0 + PSEG; p += U) {
        float v[U];
        #pragma unroll
        for (int u = 0; u < U; u++)
            v[u] = ip[(size_t)(p + u) * C];
        #pragma unroll
        for (int u = 0; u < U; u++)
            op[(size_t)(p + u) * C] = v[u];
        #pragma unroll
        for (int u = 0; u < U; u++) {
            float vv = v[u];
            if (vv > t3) {
                int pp = p + u;
                if (vv > t0) {
                    t3 = t2; i3 = i2; t2 = t1; i2 = i1; t1 = t0; i1 = i0;
                    t0 = vv; i0 = pp;
                } else if (vv > t1) {
                    t3 = t2; i3 = i2; t2 = t1; i2 = i1;
                    t1 = vv; i1 = pp;
                } else if (vv > t2) {
                    t3 = t2; i3 = i2;
                    t2 = vv; i2 = pp;
                } else {
                    t3 = vv; i3 = pp;
                }
            }
        }
    }

    // candidate exchange: [seg][rank][col] -> conflict-free for both phases
    __shared__ float sv[SEG][4][COLS];
    __shared__ int   si[SEG][4][COLS];
    sv[seg][0][lane] = t0; si[seg][0][lane] = i0;
    sv[seg][1][lane] = t1; si[seg][1][lane] = i1;
    sv[seg][2][lane] = t2; si[seg][2][lane] = i2;
    sv[seg][3][lane] = t3; si[seg][3][lane] = i3;

    __syncthreads();   // also orders this block's global copy-stores before patch

    if (tid < COLS) {
        // merge 16 candidates; stable order = (value desc, index asc)
        float m0 = -CUDART_INF_F, m1 = -CUDART_INF_F,
              m2 = -CUDART_INF_F, m3 = -CUDART_INF_F;
        int   j0 = 0x7fffffff, j1 = 0x7fffffff,
              j2 = 0x7fffffff, j3 = 0x7fffffff;
        #pragma unroll
        for (int sg = 0; sg < SEG; sg++) {
            #pragma unroll
            for (int k = 0; k < 4; k++) {
                float v = sv[sg][k][tid];
                int   i = si[sg][k][tid];
                if (v > m3 || (v == m3 && i < j3)) {
                    if (v > m0 || (v == m0 && i < j0)) {
                        m3 = m2; j3 = j2; m2 = m1; j2 = j1; m1 = m0; j1 = j0;
                        m0 = v;  j0 = i;
                    } else if (v > m1 || (v == m1 && i < j1)) {
                        m3 = m2; j3 = j2; m2 = m1; j2 = j1;
                        m1 = v;  j1 = i;
                    } else if (v > m2 || (v == m2 && i < j2)) {
                        m3 = m2; j3 = j2;
                        m2 = v;  j2 = i;
                    } else {
                        m3 = v;  j3 = i;
                    }
                }
            }
        }
        // patch winners to zero (copy-stores already ordered by the barrier)
        op[(size_t)j0 * C] = 0.0f;
        op[(size_t)j1 * C] = 0.0f;
        op[(size_t)j2 * C] = 0.0f;
        op[(size_t)j3 * C] = 0.0f;
    }
}

extern "C" void kernel_launch(void* const* d_in, const int* in_sizes, int n_in,
                              void* d_out, int out_size) {
    (void)in_sizes; (void)n_in; (void)out_size;
    const float* in  = (const float*)d_in[0];
    float*       out = (float*)d_out;
    numproto_topk_zero<<<GRID, BLK>>>(in, out);
}